// round 10
// baseline (speedup 1.0000x reference)
#include <cuda_runtime.h>

#define NBINS 15
#define BS 256
#define NACC (2 + NBINS)
#define BLOCKS_PER_SM 5
#define GRID (148 * BLOCKS_PER_SM)

// [0]=focal sum (log2 units), [1]=cp sum, [2..16]=per-bin sum of (y - p)
__device__ double g_acc[NACC];
__device__ unsigned g_count;   // zero-initialized at module load

__device__ __forceinline__ float warp_sum(float v) {
#pragma unroll
    for (int o = 16; o > 0; o >>= 1) v += __shfl_down_sync(0xffffffffu, v, o);
    return v;
}

__device__ __forceinline__ float4 ld4f(const float* base, long long boff) {
    return *(const float4*)((const char*)base + boff);
}
__device__ __forceinline__ int4 ld4i(const int* base, long long boff) {
    return *(const int4*)((const char*)base + boff);
}

__device__ __forceinline__ void process1(float p, float u, int t,
                                         float& facc, float& cacc,
                                         float* __restrict__ histcol) {
    bool pos = (t != 0);
    float tf = pos ? 1.0f : 0.0f;

    // focal in log2 units: acc += alpha*(1-pt)^2 * log2(pt+1e-12); *(-ln2) at finalize
    float pt = pos ? p : 1.0f - p;
    float om = 1.0f - pt;
    float om2 = om * om;
    if (!pos) om2 += om2;               // alpha fold: x2 for negatives
    facc = fmaf(om2, __log2f(pt + 1e-12f), facc);

    // confidence penalty: pos&p<tau -> u^2 ; !pos&p>tau -> (1-u)^2
    float v = pos ? u : 1.0f - u;
    bool cond = ((p < 0.7f) == pos);
    if (cond) cacc = fmaf(v, v, cacc);

    // ECE binning: bin = min((int)(p*15), 14); accumulate (y - p)
    int b = (int)fminf(p * 15.0f, 14.0f);
    histcol[b * BS] += tf - p;
}

__device__ __forceinline__ void process4(float4 pv, float4 uv, int4 tv,
                                         float& facc, float& cacc,
                                         float* __restrict__ colA) {
    // colB = colA + NBINS*BS (constant offset; second independent chain)
    process1(pv.x, uv.x, tv.x, facc, cacc, colA);
    process1(pv.y, uv.y, tv.y, facc, cacc, colA + NBINS * BS);
    process1(pv.z, uv.z, tv.z, facc, cacc, colA);
    process1(pv.w, uv.w, tv.w, facc, cacc, colA + NBINS * BS);
}

__global__ void __launch_bounds__(BS, BLOCKS_PER_SM) fcl_main(
    const float* __restrict__ p_hat, const float* __restrict__ u_hat,
    const int* __restrict__ targets, float* __restrict__ out, int n)
{
    // histA and histB contiguous: one base pointer, constant offset between chains
    __shared__ float hist[2 * NBINS * BS];
    __shared__ float red[2][BS / 32];
    __shared__ bool is_last;

    const int tid  = threadIdx.x;
    const int lane = tid & 31;
    const int warp = tid >> 5;
    float* colA = &hist[tid];

#pragma unroll
    for (int b = 0; b < 2 * NBINS; b++) hist[b * BS + tid] = 0.0f;
    __syncthreads();

    float facc = 0.0f, cacc = 0.0f;

    const int n4 = n >> 2;
    const long long endoff = (long long)n4 * 16;
    const long long bstride = (long long)GRID * BS * 16;   // byte stride per grid step
    long long off = ((long long)blockIdx.x * BS + tid) * 16;

    // 2-deep register pipeline: 6 LDG.128 in flight per warp. Single byte
    // offset per stage shared by all three streams to minimize address regs.
    if (off < endoff) {
        const int iters = (int)((endoff - off + bstride - 1) / bstride);   // >= 1
        float4 pA, uA, pB, uB; int4 tA, tB;
        pA = ld4f(p_hat, off); uA = ld4f(u_hat, off); tA = ld4i(targets, off);
        if (iters >= 2) {
            long long o1 = off + bstride;
            pB = ld4f(p_hat, o1); uB = ld4f(u_hat, o1); tB = ld4i(targets, o1);
        }
        int it = 0;
        long long o2 = off + 2 * bstride;
        for (; it + 3 < iters; it += 2, o2 += 2 * bstride) {
            float4 pn = ld4f(p_hat, o2);
            float4 un = ld4f(u_hat, o2);
            int4   tn = ld4i(targets, o2);
            float4 pm = ld4f(p_hat, o2 + bstride);
            float4 um = ld4f(u_hat, o2 + bstride);
            int4   tm = ld4i(targets, o2 + bstride);
            process4(pA, uA, tA, facc, cacc, colA);
            process4(pB, uB, tB, facc, cacc, colA);
            pA = pn; uA = un; tA = tn;
            pB = pm; uB = um; tB = tm;
        }
        // epilogue: rem in {1,2,3}
        int rem = iters - it;
        process4(pA, uA, tA, facc, cacc, colA);
        if (rem >= 2) process4(pB, uB, tB, facc, cacc, colA);
        if (rem >= 3) {
            float4 pc = ld4f(p_hat, o2);
            float4 uc = ld4f(u_hat, o2);
            int4   tc = ld4i(targets, o2);
            process4(pc, uc, tc, facc, cacc, colA);
        }
    }
    // scalar tail (n not divisible by 4)
    {
        const int stride = GRID * BS;
        for (int j = (n4 << 2) + blockIdx.x * BS + tid; j < n; j += stride) {
            process1(p_hat[j], u_hat[j], targets[j], facc, cacc, colA);
        }
    }
    __syncthreads();

    // block-reduce focal / cp
    facc = warp_sum(facc);
    cacc = warp_sum(cacc);
    if (lane == 0) { red[0][warp] = facc; red[1][warp] = cacc; }
    __syncthreads();
    if (warp == 0) {
        float f = (lane < BS / 32) ? red[0][lane] : 0.0f;
        float c = (lane < BS / 32) ? red[1][lane] : 0.0f;
        f = warp_sum(f);
        c = warp_sum(c);
        if (lane == 0) {
            atomicAdd(&g_acc[0], (double)f);
            atomicAdd(&g_acc[1], (double)c);
        }
    }

    // block-reduce each bin column (both chains), one double atomic per bin per block
    for (int b = warp; b < NBINS; b += BS / 32) {
        float s = 0.0f;
#pragma unroll
        for (int j = lane; j < BS; j += 32)
            s += hist[b * BS + j] + hist[(NBINS + b) * BS + j];
        s = warp_sum(s);
        if (lane == 0) atomicAdd(&g_acc[2 + b], (double)s);
    }

    // last-block-done: finalize + reset accumulators for next graph replay
    __threadfence();
    if (tid == 0) {
        unsigned v = atomicInc(&g_count, GRID - 1);  // wraps to 0 on last block
        is_last = (v == GRID - 1);
    }
    __syncthreads();
    if (is_last && tid == 0) {
        double invn  = 1.0 / (double)n;
        double focal = -0.6931471805599453 * g_acc[0] * invn;  // -ln2 * log2-units
        double cp    = g_acc[1] * invn;
        double e     = 0.0;
#pragma unroll
        for (int b = 0; b < NBINS; b++) e += fabs(g_acc[2 + b]);
        e *= invn;
        out[0] = (float)(focal + 6.0 * cp + 5.0 * e);
#pragma unroll
        for (int a = 0; a < NACC; a++) g_acc[a] = 0.0;
    }
}

extern "C" void kernel_launch(void* const* d_in, const int* in_sizes, int n_in,
                              void* d_out, int out_size) {
    const float* p_hat   = (const float*)d_in[0];
    const float* u_hat   = (const float*)d_in[1];
    const int*   targets = (const int*)d_in[2];
    float* out = (float*)d_out;
    int n = in_sizes[0];

    fcl_main<<<GRID, BS>>>(p_hat, u_hat, targets, out, n);
}

// round 11
// speedup vs baseline: 1.6242x; 1.6242x over previous
#include <cuda_runtime.h>

#define NBINS 15
#define BS 256
#define NACC (2 + NBINS)
#define GRID 592            // 148 SMs * 4 blocks
#define STAGES 3
#define TILE_BYTES 4096     // 256 threads * 16B per array per stage
#define STAGE_TX (3 * TILE_BYTES)

// dynamic smem layout (bytes)
#define OFF_P    0
#define OFF_U    (OFF_P + STAGES * TILE_BYTES)      // 12288
#define OFF_T    (OFF_U + STAGES * TILE_BYTES)      // 24576
#define OFF_HIST (OFF_T + STAGES * TILE_BYTES)      // 36864
#define OFF_RED  (OFF_HIST + NBINS * BS * 4)        // 52224
#define OFF_MBAR (OFF_RED + 64)                     // 52288
#define OFF_LAST (OFF_MBAR + STAGES * 8)            // 52312
#define SMEM_TOTAL 52352

// [0]=focal sum (log2 units), [1]=cp sum, [2..16]=per-bin sum of (y - p)
__device__ double g_acc[NACC];
__device__ unsigned g_count;   // zero-initialized at module load

__device__ __forceinline__ float warp_sum(float v) {
#pragma unroll
    for (int o = 16; o > 0; o >>= 1) v += __shfl_down_sync(0xffffffffu, v, o);
    return v;
}

__device__ __forceinline__ void mbar_init(unsigned mbar, unsigned count) {
    asm volatile("mbarrier.init.shared.b64 [%0], %1;" :: "r"(mbar), "r"(count) : "memory");
}
__device__ __forceinline__ void mbar_expect(unsigned mbar, unsigned bytes) {
    asm volatile("mbarrier.arrive.expect_tx.shared.b64 _, [%0], %1;"
                 :: "r"(mbar), "r"(bytes) : "memory");
}
__device__ __forceinline__ void mbar_wait(unsigned mbar, unsigned parity) {
    asm volatile(
        "{\n\t"
        ".reg .pred P;\n\t"
        "WAIT_%=:\n\t"
        "mbarrier.try_wait.parity.shared.b64 P, [%0], %1, 0x989680;\n\t"
        "@P bra DONE_%=;\n\t"
        "bra WAIT_%=;\n\t"
        "DONE_%=:\n\t"
        "}"
        :: "r"(mbar), "r"(parity) : "memory");
}
__device__ __forceinline__ void bulk_g2s(unsigned dst, const void* src,
                                         unsigned bytes, unsigned mbar) {
    asm volatile("cp.async.bulk.shared::cluster.global.mbarrier::complete_tx::bytes "
                 "[%0], [%1], %2, [%3];"
                 :: "r"(dst), "l"(src), "r"(bytes), "r"(mbar) : "memory");
}
__device__ __forceinline__ void fence_proxy_async_cta() {
    asm volatile("fence.proxy.async.shared::cta;" ::: "memory");
}

__device__ __forceinline__ void process1(float p, float u, int t,
                                         float& facc, float& cacc,
                                         float* __restrict__ histcol) {
    bool pos = (t != 0);
    float tf = pos ? 1.0f : 0.0f;

    // focal in log2 units: acc += alpha*(1-pt)^2 * log2(pt+1e-12); *(-ln2) at finalize
    float pt = pos ? p : 1.0f - p;
    float om = 1.0f - pt;
    float om2 = om * om;
    if (!pos) om2 += om2;               // alpha fold: x2 for negatives
    facc = fmaf(om2, __log2f(pt + 1e-12f), facc);

    // confidence penalty: pos&p<tau -> u^2 ; !pos&p>tau -> (1-u)^2
    float v = pos ? u : 1.0f - u;
    bool cond = ((p < 0.7f) == pos);
    if (cond) cacc = fmaf(v, v, cacc);

    // ECE binning: bin = min((int)(p*15), 14); accumulate (y - p)
    int b = (int)fminf(p * 15.0f, 14.0f);
    histcol[b * BS] += tf - p;
}

__global__ void __launch_bounds__(BS) fcl_main(
    const float* __restrict__ p_hat, const float* __restrict__ u_hat,
    const int* __restrict__ targets, float* __restrict__ out, int n)
{
    extern __shared__ char dsm[];
    float4* sp  = (float4*)(dsm + OFF_P);
    float4* su4 = (float4*)(dsm + OFF_U);
    int4*   st4 = (int4*)(dsm + OFF_T);
    float*  hist = (float*)(dsm + OFF_HIST);
    float*  red  = (float*)(dsm + OFF_RED);
    int*    last_flag = (int*)(dsm + OFF_LAST);

    const unsigned mbar0 = (unsigned)__cvta_generic_to_shared(dsm + OFF_MBAR);
    const unsigned sp_a  = (unsigned)__cvta_generic_to_shared(dsm + OFF_P);
    const unsigned su_a  = (unsigned)__cvta_generic_to_shared(dsm + OFF_U);
    const unsigned st_a  = (unsigned)__cvta_generic_to_shared(dsm + OFF_T);

    const int tid  = threadIdx.x;
    const int lane = tid & 31;
    const int warp = tid >> 5;
    float* col = &hist[tid];

#pragma unroll
    for (int b = 0; b < NBINS; b++) hist[b * BS + tid] = 0.0f;
    if (tid == 0) {
#pragma unroll
        for (int s = 0; s < STAGES; s++) mbar_init(mbar0 + s * 8, 1);
    }
    __syncthreads();   // hist zeroed + mbarriers initialized

    const int n4 = n >> 2;
    const int T4 = n4 >> 8;                 // full 256-float4 tiles
    int myTiles = (blockIdx.x < T4) ? (T4 - blockIdx.x + GRID - 1) / GRID : 0;

    // prologue: stage first min(STAGES, myTiles) tiles
    if (tid == 0) {
        int pre = myTiles < STAGES ? myTiles : STAGES;
        for (int k = 0; k < pre; k++) {
            unsigned mb = mbar0 + k * 8;
            long long goff = ((long long)blockIdx.x + (long long)k * GRID) * TILE_BYTES;
            mbar_expect(mb, STAGE_TX);
            bulk_g2s(sp_a + k * TILE_BYTES, (const char*)p_hat  + goff, TILE_BYTES, mb);
            bulk_g2s(su_a + k * TILE_BYTES, (const char*)u_hat  + goff, TILE_BYTES, mb);
            bulk_g2s(st_a + k * TILE_BYTES, (const char*)targets + goff, TILE_BYTES, mb);
        }
    }

    float facc = 0.0f, cacc = 0.0f;

    int s = 0, parity = 0;
    for (int it = 0; it < myTiles; it++) {
        unsigned mb = mbar0 + s * 8;
        mbar_wait(mb, parity);                      // stage data landed
        float4 pv = sp [s * BS + tid];
        float4 uv = su4[s * BS + tid];
        int4   tv = st4[s * BS + tid];
        __syncthreads();                            // all reads of stage s done
        int nt = it + STAGES;
        if (tid == 0 && nt < myTiles) {             // refill stage s with tile it+3
            fence_proxy_async_cta();
            long long goff = ((long long)blockIdx.x + (long long)nt * GRID) * TILE_BYTES;
            mbar_expect(mb, STAGE_TX);
            bulk_g2s(sp_a + s * TILE_BYTES, (const char*)p_hat  + goff, TILE_BYTES, mb);
            bulk_g2s(su_a + s * TILE_BYTES, (const char*)u_hat  + goff, TILE_BYTES, mb);
            bulk_g2s(st_a + s * TILE_BYTES, (const char*)targets + goff, TILE_BYTES, mb);
        }
        process1(pv.x, uv.x, tv.x, facc, cacc, col);
        process1(pv.y, uv.y, tv.y, facc, cacc, col);
        process1(pv.z, uv.z, tv.z, facc, cacc, col);
        process1(pv.w, uv.w, tv.w, facc, cacc, col);
        if (++s == STAGES) { s = 0; parity ^= 1; }
    }

    // epilogue: elements beyond the full-tile region (vector-tail + scalar-tail)
    {
        const int stride = GRID * BS;
        for (int j = (T4 << 10) + blockIdx.x * BS + tid; j < n; j += stride) {
            process1(p_hat[j], u_hat[j], targets[j], facc, cacc, col);
        }
    }
    __syncthreads();

    // block-reduce focal / cp
    facc = warp_sum(facc);
    cacc = warp_sum(cacc);
    if (lane == 0) { red[warp] = facc; red[8 + warp] = cacc; }
    __syncthreads();
    if (warp == 0) {
        float f = (lane < 8) ? red[lane] : 0.0f;
        float c = (lane < 8) ? red[8 + lane] : 0.0f;
        f = warp_sum(f);
        c = warp_sum(c);
        if (lane == 0) {
            atomicAdd(&g_acc[0], (double)f);
            atomicAdd(&g_acc[1], (double)c);
        }
    }

    // block-reduce each bin column, one double atomic per bin per block
    for (int b = warp; b < NBINS; b += 8) {
        float sv = 0.0f;
#pragma unroll
        for (int j = lane; j < BS; j += 32) sv += hist[b * BS + j];
        sv = warp_sum(sv);
        if (lane == 0) atomicAdd(&g_acc[2 + b], (double)sv);
    }

    // last-block-done: finalize + reset accumulators for next graph replay
    __threadfence();
    if (tid == 0) {
        unsigned v = atomicInc(&g_count, GRID - 1);  // wraps to 0 on last block
        *last_flag = (v == GRID - 1);
    }
    __syncthreads();
    if (*last_flag && tid == 0) {
        double invn  = 1.0 / (double)n;
        double focal = -0.6931471805599453 * g_acc[0] * invn;  // -ln2 * log2-units
        double cp    = g_acc[1] * invn;
        double e     = 0.0;
#pragma unroll
        for (int b = 0; b < NBINS; b++) e += fabs(g_acc[2 + b]);
        e *= invn;
        out[0] = (float)(focal + 6.0 * cp + 5.0 * e);
#pragma unroll
        for (int a = 0; a < NACC; a++) g_acc[a] = 0.0;
    }
}

extern "C" void kernel_launch(void* const* d_in, const int* in_sizes, int n_in,
                              void* d_out, int out_size) {
    const float* p_hat   = (const float*)d_in[0];
    const float* u_hat   = (const float*)d_in[1];
    const int*   targets = (const int*)d_in[2];
    float* out = (float*)d_out;
    int n = in_sizes[0];

    static bool attr_done = false;
    if (!attr_done) {
        cudaFuncSetAttribute(fcl_main, cudaFuncAttributeMaxDynamicSharedMemorySize,
                             SMEM_TOTAL);
        attr_done = true;
    }
    fcl_main<<<GRID, BS, SMEM_TOTAL>>>(p_hat, u_hat, targets, out, n);
}

// round 12
// speedup vs baseline: 1.7375x; 1.0697x over previous
#include <cuda_runtime.h>

#define NBINS 15
#define NC 256              // consumer threads
#define BSALL 288           // 8 consumer warps + 1 producer warp
#define NACC (2 + NBINS)
#define GRID 296            // 148 SMs * 2 blocks
#define STAGES 8
#define TILE_BYTES 4096     // 256 lanes * 16B per array per stage
#define STAGE_TX (3 * TILE_BYTES)

// dynamic smem layout (bytes)
#define OFF_P    0
#define OFF_U    (OFF_P + STAGES * TILE_BYTES)      // 32768
#define OFF_T    (OFF_U + STAGES * TILE_BYTES)      // 65536
#define OFF_HIST (OFF_T + STAGES * TILE_BYTES)      // 98304
#define OFF_RED  (OFF_HIST + NBINS * NC * 4)        // 113664 (9x2 floats)
#define OFF_FULL (OFF_RED + 96)                     // 113760
#define OFF_CONS (OFF_FULL + STAGES * 8)            // 113824
#define OFF_LAST (OFF_CONS + STAGES * 8)            // 113888
#define SMEM_TOTAL 113920

// [0]=focal sum (log2 units), [1]=cp sum, [2..16]=per-bin sum of (y - p)
__device__ double g_acc[NACC];
__device__ unsigned g_count;   // zero-initialized at module load

__device__ __forceinline__ float warp_sum(float v) {
#pragma unroll
    for (int o = 16; o > 0; o >>= 1) v += __shfl_down_sync(0xffffffffu, v, o);
    return v;
}

__device__ __forceinline__ void mbar_init(unsigned mbar, unsigned count) {
    asm volatile("mbarrier.init.shared.b64 [%0], %1;" :: "r"(mbar), "r"(count) : "memory");
}
__device__ __forceinline__ void mbar_expect(unsigned mbar, unsigned bytes) {
    asm volatile("mbarrier.arrive.expect_tx.shared.b64 _, [%0], %1;"
                 :: "r"(mbar), "r"(bytes) : "memory");
}
__device__ __forceinline__ void mbar_arrive(unsigned mbar) {
    asm volatile("mbarrier.arrive.shared.b64 _, [%0];" :: "r"(mbar) : "memory");
}
__device__ __forceinline__ void mbar_wait(unsigned mbar, unsigned parity) {
    asm volatile(
        "{\n\t"
        ".reg .pred P;\n\t"
        "WAIT_%=:\n\t"
        "mbarrier.try_wait.parity.shared.b64 P, [%0], %1, 0x989680;\n\t"
        "@P bra DONE_%=;\n\t"
        "bra WAIT_%=;\n\t"
        "DONE_%=:\n\t"
        "}"
        :: "r"(mbar), "r"(parity) : "memory");
}
__device__ __forceinline__ void bulk_g2s(unsigned dst, const void* src,
                                         unsigned bytes, unsigned mbar) {
    asm volatile("cp.async.bulk.shared::cluster.global.mbarrier::complete_tx::bytes "
                 "[%0], [%1], %2, [%3];"
                 :: "r"(dst), "l"(src), "r"(bytes), "r"(mbar) : "memory");
}
__device__ __forceinline__ void fence_proxy_async_cta() {
    asm volatile("fence.proxy.async.shared::cta;" ::: "memory");
}

__device__ __forceinline__ void process1(float p, float u, int t,
                                         float& facc, float& cacc,
                                         float* __restrict__ histcol) {
    bool pos = (t != 0);
    float tf = pos ? 1.0f : 0.0f;

    // focal in log2 units: acc += alpha*(1-pt)^2 * log2(pt+1e-12); *(-ln2) at finalize
    float pt = pos ? p : 1.0f - p;
    float om = 1.0f - pt;
    float om2 = om * om;
    if (!pos) om2 += om2;               // alpha fold: x2 for negatives
    facc = fmaf(om2, __log2f(pt + 1e-12f), facc);

    // confidence penalty: pos&p<tau -> u^2 ; !pos&p>tau -> (1-u)^2
    float v = pos ? u : 1.0f - u;
    bool cond = ((p < 0.7f) == pos);
    if (cond) cacc = fmaf(v, v, cacc);

    // ECE binning: bin = min((int)(p*15), 14); accumulate (y - p)
    int b = (int)fminf(p * 15.0f, 14.0f);
    histcol[b * NC] += tf - p;
}

__global__ void __launch_bounds__(BSALL) fcl_main(
    const float* __restrict__ p_hat, const float* __restrict__ u_hat,
    const int* __restrict__ targets, float* __restrict__ out, int n)
{
    extern __shared__ char dsm[];
    float4* sp  = (float4*)(dsm + OFF_P);
    float4* su4 = (float4*)(dsm + OFF_U);
    int4*   st4 = (int4*)(dsm + OFF_T);
    float*  hist = (float*)(dsm + OFF_HIST);
    float*  red  = (float*)(dsm + OFF_RED);
    int*    last_flag = (int*)(dsm + OFF_LAST);

    const unsigned full0 = (unsigned)__cvta_generic_to_shared(dsm + OFF_FULL);
    const unsigned cons0 = (unsigned)__cvta_generic_to_shared(dsm + OFF_CONS);
    const unsigned sp_a  = (unsigned)__cvta_generic_to_shared(dsm + OFF_P);
    const unsigned su_a  = (unsigned)__cvta_generic_to_shared(dsm + OFF_U);
    const unsigned st_a  = (unsigned)__cvta_generic_to_shared(dsm + OFF_T);

    const int tid  = threadIdx.x;
    const int lane = tid & 31;
    const int warp = tid >> 5;          // 0..8

    if (tid < NC) {
#pragma unroll
        for (int b = 0; b < NBINS; b++) hist[b * NC + tid] = 0.0f;
    }
    if (tid == 0) {
#pragma unroll
        for (int s = 0; s < STAGES; s++) {
            mbar_init(full0 + s * 8, 1);     // producer's expect_tx completes it
            mbar_init(cons0 + s * 8, NC);    // all consumer threads arrive
        }
    }
    __syncthreads();   // hist zeroed + mbarriers initialized

    const int n4 = n >> 2;
    const int T4 = n4 >> 8;                  // full 256-float4 tiles
    const int myTiles = (blockIdx.x < T4) ? (T4 - blockIdx.x + GRID - 1) / GRID : 0;

    float facc = 0.0f, cacc = 0.0f;

    if (warp == 8) {
        // ---- producer warp: free-running TMA refill, gated by consumed bars ----
        if (lane == 0) {
            int s = 0, wc = 0, wp = 0;
            for (int k = 0; k < myTiles; k++) {
                if (k >= STAGES) mbar_wait(cons0 + s * 8, wp);  // stage drained
                fence_proxy_async_cta();
                long long goff = ((long long)blockIdx.x + (long long)k * GRID) * TILE_BYTES;
                unsigned mb = full0 + s * 8;
                mbar_expect(mb, STAGE_TX);
                bulk_g2s(sp_a + s * TILE_BYTES, (const char*)p_hat   + goff, TILE_BYTES, mb);
                bulk_g2s(su_a + s * TILE_BYTES, (const char*)u_hat   + goff, TILE_BYTES, mb);
                bulk_g2s(st_a + s * TILE_BYTES, (const char*)targets + goff, TILE_BYTES, mb);
                if (++s == STAGES) { s = 0; wc++; wp = (wc - 1) & 1; }
            }
        }
    } else {
        // ---- consumer warps ----
        float* col = &hist[tid];
        int s = 0, fp = 0;
        for (int it = 0; it < myTiles; it++) {
            mbar_wait(full0 + s * 8, fp);           // stage data landed
            float4 pv = sp [s * NC + tid];
            float4 uv = su4[s * NC + tid];
            int4   tv = st4[s * NC + tid];
            mbar_arrive(cons0 + s * 8);             // my reads done; stage may refill
            process1(pv.x, uv.x, tv.x, facc, cacc, col);
            process1(pv.y, uv.y, tv.y, facc, cacc, col);
            process1(pv.z, uv.z, tv.z, facc, cacc, col);
            process1(pv.w, uv.w, tv.w, facc, cacc, col);
            if (++s == STAGES) { s = 0; fp ^= 1; }
        }
        // epilogue: elements beyond the full-tile region
        for (int j = (T4 << 10) + blockIdx.x * NC + tid; j < n; j += GRID * NC) {
            process1(p_hat[j], u_hat[j], targets[j], facc, cacc, col);
        }
    }
    __syncthreads();

    // block-reduce focal / cp (producer warp contributes zeros)
    facc = warp_sum(facc);
    cacc = warp_sum(cacc);
    if (lane == 0) { red[warp] = facc; red[9 + warp] = cacc; }
    __syncthreads();
    if (warp == 0) {
        float f = (lane < 9) ? red[lane] : 0.0f;
        float c = (lane < 9) ? red[9 + lane] : 0.0f;
        f = warp_sum(f);
        c = warp_sum(c);
        if (lane == 0) {
            atomicAdd(&g_acc[0], (double)f);
            atomicAdd(&g_acc[1], (double)c);
        }
    }

    // block-reduce each bin column (9 warps cover 15 bins)
    for (int b = warp; b < NBINS; b += 9) {
        float sv = 0.0f;
#pragma unroll
        for (int j = lane; j < NC; j += 32) sv += hist[b * NC + j];
        sv = warp_sum(sv);
        if (lane == 0) atomicAdd(&g_acc[2 + b], (double)sv);
    }

    // last-block-done: finalize + reset accumulators for next graph replay
    __threadfence();
    if (tid == 0) {
        unsigned v = atomicInc(&g_count, GRID - 1);  // wraps to 0 on last block
        *last_flag = (v == GRID - 1);
    }
    __syncthreads();
    if (*last_flag && tid == 0) {
        double invn  = 1.0 / (double)n;
        double focal = -0.6931471805599453 * g_acc[0] * invn;  // -ln2 * log2-units
        double cp    = g_acc[1] * invn;
        double e     = 0.0;
#pragma unroll
        for (int b = 0; b < NBINS; b++) e += fabs(g_acc[2 + b]);
        e *= invn;
        out[0] = (float)(focal + 6.0 * cp + 5.0 * e);
#pragma unroll
        for (int a = 0; a < NACC; a++) g_acc[a] = 0.0;
    }
}

extern "C" void kernel_launch(void* const* d_in, const int* in_sizes, int n_in,
                              void* d_out, int out_size) {
    const float* p_hat   = (const float*)d_in[0];
    const float* u_hat   = (const float*)d_in[1];
    const int*   targets = (const int*)d_in[2];
    float* out = (float*)d_out;
    int n = in_sizes[0];

    static bool attr_done = false;
    if (!attr_done) {
        cudaFuncSetAttribute(fcl_main, cudaFuncAttributeMaxDynamicSharedMemorySize,
                             SMEM_TOTAL);
        attr_done = true;
    }
    fcl_main<<<GRID, BSALL, SMEM_TOTAL>>>(p_hat, u_hat, targets, out, n);
}